// round 11
// baseline (speedup 1.0000x reference)
#include <cuda_runtime.h>
#include <math.h>

#define HH 480
#define WW 640
#define NPIX (HH*WW)          // 307200
#define VOXN 800000           // 100*100*80
#define MM 960
#define MPIX (MM*MM)          // 921600
#define FP_OFF 0
#define MAP_OFF 10000
#define POSE_OFF (10000 + 9*MPIX)   // 8304400

// scratch (device globals: allocation-free, zero-initialized at load)
__device__ float g_vox[6*VOXN];          // 19.2 MB voxel grid
__device__ float g_av[7*10000];          // agent_view active region, ch {0,1,4,5,6,7,8}
__device__ float g_rot[7*MPIX];          // rotated image (only bbox ever written)
__device__ unsigned int g_ksbits[4];
__device__ float g_params[12];           // 0:f 1:ct 2:sn 3:sx 4:sy 5..8: bbox

// ---------------------------------------------------------------- zero
__global__ void zero_kernel() {
    int i = blockIdx.x*blockDim.x + threadIdx.x;
    if (i < (6*VOXN)/4) reinterpret_cast<float4*>(g_vox)[i] = make_float4(0.f,0.f,0.f,0.f);
    if (i < 4) g_ksbits[i] = 0u;
}

// ---------------------------------------------------------------- pose + transform params
__global__ void pose_kernel(const float* __restrict__ pose_obs,
                            const float* __restrict__ poses_last,
                            float* __restrict__ out) {
    const float DEGf = 57.29577951308232f;
    float th = poses_last[2] / DEGf;
    float s = sinf(th), c = cosf(th);
    float ny = poses_last[1] + pose_obs[0]*s + pose_obs[1]*c;
    float nx = poses_last[0] + pose_obs[0]*c - pose_obs[1]*s;
    float nt = poses_last[2] + pose_obs[2]*DEGf;
    nt = fmodf(nt - 180.0f, 360.0f) + 180.0f;
    nt = fmodf(nt + 180.0f, 360.0f) - 180.0f;
    out[POSE_OFF+0] = nx; out[POSE_OFF+1] = ny; out[POSE_OFF+2] = nt;
    out[POSE_OFF+3] = nx; out[POSE_OFF+4] = ny; out[POSE_OFF+5] = nt;

    float sx = -(nx*100.0f/5.0f - 480.0f)/480.0f;
    float sy = -(ny*100.0f/5.0f - 480.0f)/480.0f;
    float sth = (90.0f - nt) * 3.14159265358979323846f / 180.0f;
    float ct = cosf(sth), sn = sinf(sth);
    // camera focal length, float64 math then cast (matches numpy host compute)
    double fd = 320.0 / tan(39.5 * 3.14159265358979323846 / 180.0);
    g_params[0] = (float)fd;
    g_params[1] = ct; g_params[2] = sn;
    g_params[3] = sx; g_params[4] = sy;

    // bbox of rotated nonzero support: inverse-rotate region corners
    // active region (+1 bilinear margin): x in (429,530), y in (479,580)
    const float half = 479.5f;
    float xmn=1e9f,xmx=-1e9f,ymn=1e9f,ymx=-1e9f;
    float cx[4] = {429.f,530.f,429.f,530.f};
    float cy[4] = {479.f,479.f,580.f,580.f};
    #pragma unroll
    for (int k=0;k<4;k++){
        float u = cx[k]/half - 1.0f, v = cy[k]/half - 1.0f;
        float gu =  ct*u + sn*v;
        float gv = -sn*u + ct*v;
        float jx = (gu+1.0f)*half, iy = (gv+1.0f)*half;
        xmn = fminf(xmn,jx); xmx = fmaxf(xmx,jx);
        ymn = fminf(ymn,iy); ymx = fmaxf(ymx,iy);
    }
    g_params[5] = fmaxf(floorf(xmn)-3.0f, 0.0f);
    g_params[6] = fminf(ceilf (xmx)+3.0f, 959.0f);
    g_params[7] = fmaxf(floorf(ymn)-3.0f, 0.0f);
    g_params[8] = fminf(ceilf (ymx)+3.0f, 959.0f);
}

// ---------------------------------------------------------------- ks = per-channel max of obs[4..7]
__global__ __launch_bounds__(256) void ks_kernel(const float* __restrict__ obs) {
    int ch = blockIdx.y;
    const float* p = obs + (4+ch)*NPIX;
    float m = 0.0f;
    for (int idx = blockIdx.x*blockDim.x + threadIdx.x; idx < NPIX; idx += gridDim.x*blockDim.x)
        m = fmaxf(m, p[idx]);
    #pragma unroll
    for (int off=16; off; off>>=1) m = fmaxf(m, __shfl_xor_sync(0xffffffffu, m, off));
    __shared__ float sm[8];
    int lane = threadIdx.x & 31, wid = threadIdx.x >> 5;
    if (lane == 0) sm[wid] = m;
    __syncthreads();
    if (threadIdx.x == 0) {
        float v = sm[0];
        #pragma unroll
        for (int k=1;k<8;k++) v = fmaxf(v, sm[k]);
        atomicMax(&g_ksbits[ch], __float_as_uint(v));   // non-negative floats
    }
}

// ---------------------------------------------------------------- trilinear splat (scatter-add)
__global__ __launch_bounds__(256) void splat_kernel(const float* __restrict__ obs) {
    int pix = blockIdx.x*blockDim.x + threadIdx.x;
    if (pix >= NPIX) return;
    int i = pix / WW, j = pix - i*WW;
    float fcam = g_params[0];
    float depth = obs[3*NPIX + pix];
    float X = ((float)j - 319.5f) * depth / fcam + 250.0f;
    float Z = ((float)(479 - i) - 239.5f) * depth / fcam + 88.0f;
    float xs = (X/5.0f - 50.0f)/100.0f*2.0f;
    float ys = (depth/5.0f - 50.0f)/100.0f*2.0f;
    float zs = (Z/5.0f - 32.0f)/80.0f*2.0f;
    float pos0 = xs*100.0f/2.0f + 50.0f;
    float pos1 = ys*100.0f/2.0f + 50.0f;
    float pos2 = zs*80.0f/2.0f + 40.0f;
    float fl0 = floorf(pos0), fl1 = floorf(pos1), fl2 = floorf(pos2);
    float ft1 = obs[4*NPIX+pix], ft2 = obs[5*NPIX+pix], ft3 = obs[6*NPIX+pix];
    float ft4 = obs[7*NPIX+pix], ft5 = obs[8*NPIX+pix];
    #pragma unroll
    for (int c0=0;c0<2;c0++){
        float p0 = fl0 + (float)c0;
        if (!(p0 > 0.0f && p0 < 100.0f)) continue;
        float w0 = 1.0f - fabsf(pos0 - p0);
        #pragma unroll
        for (int c1=0;c1<2;c1++){
            float p1 = fl1 + (float)c1;
            if (!(p1 > 0.0f && p1 < 100.0f)) continue;
            float w01 = w0 * (1.0f - fabsf(pos1 - p1));
            #pragma unroll
            for (int c2=0;c2<2;c2++){
                float p2 = fl2 + (float)c2;
                if (!(p2 > 0.0f && p2 < 80.0f)) continue;
                float w = w01 * (1.0f - fabsf(pos2 - p2));
                int idx = (((int)p0)*100 + (int)p1)*80 + (int)p2;
                atomicAdd(&g_vox[          idx],     w);
                atomicAdd(&g_vox[  VOXN + idx], ft1*w);
                atomicAdd(&g_vox[2*VOXN + idx], ft2*w);
                atomicAdd(&g_vox[3*VOXN + idx], ft3*w);
                atomicAdd(&g_vox[4*VOXN + idx], ft4*w);
                atomicAdd(&g_vox[5*VOXN + idx], ft5*w);
            }
        }
    }
}

// ---------------------------------------------------------------- round + z-sums -> agent_view channels
__global__ __launch_bounds__(256) void reduce_kernel(float* __restrict__ out_fp) {
    int t = blockIdx.x*blockDim.x + threadIdx.x;
    if (t >= 10000) return;
    int a = t / 100, b = t - a*100;           // a = y (depth) idx, b = x idx
    float res[7];
    #pragma unroll
    for (int f=0; f<6; f++){
        const float* src = g_vox + f*VOXN + (b*100 + a)*80;  // voxels[f, x=b, y=a, z]
        float allv = 0.f, ah = 0.f;
        #pragma unroll 8
        for (int z=0; z<80; z++){
            float v = rintf(src[z]);          // round-half-to-even, matches jnp.round
            allv += v;
            if (z >= 13 && z < 25) ah += v;
        }
        if (f == 0) {
            res[0] = fminf(fmaxf(ah,   0.f), 1.f);   // fp_map
            res[1] = fminf(fmaxf(allv, 0.f), 1.f);   // fp_exp
        } else {
            res[1+f] = fminf(fmaxf(ah/5.0f, 0.f), 1.f);  // channels 4..8
        }
    }
    #pragma unroll
    for (int c=0;c<7;c++) g_av[c*10000 + t] = res[c];
    out_fp[t] = res[0];
}

// ---------------------------------------------------------------- rotation resample (bbox only)
__global__ __launch_bounds__(256) void rotate_kernel() {
    int pix = blockIdx.x*blockDim.x + threadIdx.x;
    if (pix >= MPIX) return;
    int i = pix / MM, j = pix - i*MM;
    int xmin = (int)g_params[5], xmax = (int)g_params[6];
    int ymin = (int)g_params[7], ymax = (int)g_params[8];
    if (j < xmin || j > xmax || i < ymin || i > ymax) return;  // outside: stays zero-init
    float ct = g_params[1], sn = g_params[2];
    const float step = 2.0f/959.0f;
    float gx = -1.0f + (float)j*step;
    float gy = -1.0f + (float)i*step;
    float x = (ct*gx - sn*gy + 1.0f)*0.5f*959.0f;
    float y = (sn*gx + ct*gy + 1.0f)*0.5f*959.0f;
    float x0 = floorf(x), y0 = floorf(y);
    float acc[7] = {0.f,0.f,0.f,0.f,0.f,0.f,0.f};
    #pragma unroll
    for (int dy=0; dy<2; dy++){
        float yy = y0 + (float)dy;
        int yi = (int)yy;
        #pragma unroll
        for (int dx=0; dx<2; dx++){
            float xx = x0 + (float)dx;
            int xi = (int)xx;
            if (yi >= 480 && yi < 580 && xi >= 430 && xi < 530) {
                float wv = (1.0f - fabsf(x - xx)) * (1.0f - fabsf(y - yy));
                int o = (yi - 480)*100 + (xi - 430);
                #pragma unroll
                for (int c=0;c<7;c++) acc[c] += g_av[c*10000 + o] * wv;
            }
        }
    }
    #pragma unroll
    for (int c=0;c<7;c++) g_rot[c*MPIX + pix] = acc[c];
}

// ---------------------------------------------------------------- translate + sem replace + max(maps_last)
__global__ __launch_bounds__(256) void translate_kernel(const float* __restrict__ maps_last,
                                                        float* __restrict__ out_map) {
    int pix = blockIdx.x*blockDim.x + threadIdx.x;
    if (pix >= MPIX) return;
    int i = pix / MM, j = pix - i*MM;
    const float step = 2.0f/959.0f;
    float sx = g_params[3], sy = g_params[4];
    float gx = -1.0f + (float)j*step;
    float gy = -1.0f + (float)i*step;
    float x = ((gx + sx) + 1.0f)*0.5f*959.0f;
    float y = ((gy + sy) + 1.0f)*0.5f*959.0f;
    float x0 = floorf(x), y0 = floorf(y);
    float t[7] = {0.f,0.f,0.f,0.f,0.f,0.f,0.f};
    float xminf = g_params[5], xmaxf = g_params[6];
    float yminf = g_params[7], ymaxf = g_params[8];
    // only touch g_rot if the 2x2 window can intersect the rotated support bbox
    if (!(x0 > xmaxf || x0 + 1.0f < xminf || y0 > ymaxf || y0 + 1.0f < yminf)) {
        #pragma unroll
        for (int dy=0; dy<2; dy++){
            float yy = y0 + (float)dy;
            int yi = (int)yy;
            #pragma unroll
            for (int dx=0; dx<2; dx++){
                float xx = x0 + (float)dx;
                int xi = (int)xx;
                if (xx >= 0.0f && xx <= 959.0f && yy >= 0.0f && yy <= 959.0f) {
                    float wv = (1.0f - fabsf(x - xx)) * (1.0f - fabsf(y - yy));
                    int o = yi*MM + xi;
                    #pragma unroll
                    for (int c=0;c<7;c++) t[c] += g_rot[c*MPIX + o] * wv;
                }
            }
        }
    }
    out_map[          pix] = fmaxf(maps_last[          pix], t[0]);
    out_map[  MPIX + pix] = fmaxf(maps_last[  MPIX + pix], t[1]);
    out_map[2*MPIX + pix] = fmaxf(maps_last[2*MPIX + pix], 0.0f);  // translated ch2 == 0
    out_map[3*MPIX + pix] = fmaxf(maps_last[3*MPIX + pix], 0.0f);  // translated ch3 == 0
    #pragma unroll
    for (int k=0;k<4;k++){
        float tt = t[2+k];
        if (tt > 0.0f) tt = __uint_as_float(g_ksbits[k]);           // sem replacement
        out_map[(4+k)*MPIX + pix] = fmaxf(maps_last[(4+k)*MPIX + pix], tt);
    }
    out_map[8*MPIX + pix] = fmaxf(maps_last[8*MPIX + pix], t[6]);
}

// ---------------------------------------------------------------- launch
extern "C" void kernel_launch(void* const* d_in, const int* in_sizes, int n_in,
                              void* d_out, int out_size) {
    const float* obs        = (const float*)d_in[0];   // (1,9,480,640)
    const float* pose_obs   = (const float*)d_in[1];   // (3,)
    const float* maps_last  = (const float*)d_in[2];   // (9,960,960)
    const float* poses_last = (const float*)d_in[3];   // (3,)
    float* out = (float*)d_out;

    zero_kernel<<<(6*VOXN/4 + 255)/256, 256>>>();
    pose_kernel<<<1, 1>>>(pose_obs, poses_last, out);
    dim3 ksgrid(150, 4);
    ks_kernel<<<ksgrid, 256>>>(obs);
    splat_kernel<<<(NPIX + 255)/256, 256>>>(obs);
    reduce_kernel<<<(10000 + 255)/256, 256>>>(out + FP_OFF);
    rotate_kernel<<<(MPIX + 255)/256, 256>>>();
    translate_kernel<<<(MPIX + 255)/256, 256>>>(maps_last, out + MAP_OFF);
    (void)in_sizes; (void)n_in; (void)out_size;
}

// round 12
// speedup vs baseline: 1.9860x; 1.9860x over previous
#include <cuda_runtime.h>
#include <math.h>

#define HH 480
#define WW 640
#define NPIX (HH*WW)          // 307200
#define VOXN 800000           // 100*100*80
#define MM 960
#define MPIX (MM*MM)          // 921600
#define FP_OFF 0
#define MAP_OFF 10000
#define POSE_OFF (10000 + 9*MPIX)   // 8304400
#define SPLAT_BLOCKS 1200
#define ROT_LO 360
#define ROT_W 241             // covers [360,600] inclusive

// scratch (device globals: allocation-free, zero-initialized at load)
__device__ __align__(32) float g_vox2[VOXN*8]; // interleaved [vox][8]: w,f1..f5,pad,pad (25.6MB)
__device__ float g_av[7*10000];                // agent_view active region, ch {0,1,4,5,6,7,8}
__device__ float g_rot[7*MPIX];                // rotated image (only support window ever written)
__device__ float g_bmax[4*SPLAT_BLOCKS];       // per-block ks maxes
__device__ float g_ks[4];                      // final ks
__device__ float g_params[12];                 // 1:ct 2:sn 3:sx 4:sy 5..8: bbox

__device__ __forceinline__ void red_v4(float* p, float a, float b, float c, float d) {
    asm volatile("red.global.add.v4.f32 [%0], {%1,%2,%3,%4};"
                 :: "l"(p), "f"(a), "f"(b), "f"(c), "f"(d) : "memory");
}
__device__ __forceinline__ void red_v2(float* p, float a, float b) {
    asm volatile("red.global.add.v2.f32 [%0], {%1,%2};"
                 :: "l"(p), "f"(a), "f"(b) : "memory");
}

// ---------------------------------------------------------------- splat (+pose, +ks block max)
__global__ __launch_bounds__(256) void splat_kernel(const float* __restrict__ obs,
                                                    const float* __restrict__ pose_obs,
                                                    const float* __restrict__ poses_last,
                                                    float* __restrict__ out) {
    __shared__ float sh_f;
    __shared__ float smax[8][4];
    int tid = threadIdx.x;
    if (tid == 0) {
        // fp64 once per block (avoids per-thread fp64 tan cost)
        sh_f = (float)(320.0 / tan(39.5 * 3.141592653589793 / 180.0));
        if (blockIdx.x == 0) {
            // ---- pose + transform params (matches reference numerics) ----
            const float DEGf = 57.29577951308232f;
            float th = poses_last[2] / DEGf;
            float s = sinf(th), c = cosf(th);
            float ny = poses_last[1] + pose_obs[0]*s + pose_obs[1]*c;
            float nx = poses_last[0] + pose_obs[0]*c - pose_obs[1]*s;
            float nt = poses_last[2] + pose_obs[2]*DEGf;
            nt = fmodf(nt - 180.0f, 360.0f) + 180.0f;
            nt = fmodf(nt + 180.0f, 360.0f) - 180.0f;
            out[POSE_OFF+0] = nx; out[POSE_OFF+1] = ny; out[POSE_OFF+2] = nt;
            out[POSE_OFF+3] = nx; out[POSE_OFF+4] = ny; out[POSE_OFF+5] = nt;

            float sx = -(nx*100.0f/5.0f - 480.0f)/480.0f;
            float sy = -(ny*100.0f/5.0f - 480.0f)/480.0f;
            float sth = (90.0f - nt) * 3.14159265358979323846f / 180.0f;
            float ct = cosf(sth), sn = sinf(sth);
            g_params[1] = ct; g_params[2] = sn;
            g_params[3] = sx; g_params[4] = sy;

            // bbox of rotated nonzero support (inverse-rotate region corners)
            const float half = 479.5f;
            float xmn=1e9f,xmx=-1e9f,ymn=1e9f,ymx=-1e9f;
            float cx[4] = {429.f,530.f,429.f,530.f};
            float cy[4] = {479.f,479.f,580.f,580.f};
            #pragma unroll
            for (int k=0;k<4;k++){
                float u = cx[k]/half - 1.0f, v = cy[k]/half - 1.0f;
                float gu =  ct*u + sn*v;
                float gv = -sn*u + ct*v;
                float jx = (gu+1.0f)*half, iy = (gv+1.0f)*half;
                xmn = fminf(xmn,jx); xmx = fmaxf(xmx,jx);
                ymn = fminf(ymn,iy); ymx = fmaxf(ymx,iy);
            }
            g_params[5] = fmaxf(floorf(xmn)-3.0f, 0.0f);
            g_params[6] = fminf(ceilf (xmx)+3.0f, 959.0f);
            g_params[7] = fmaxf(floorf(ymn)-3.0f, 0.0f);
            g_params[8] = fminf(ceilf (ymx)+3.0f, 959.0f);
        }
    }
    __syncthreads();
    float fcam = sh_f;

    int pix = blockIdx.x*256 + tid;             // NPIX == SPLAT_BLOCKS*256 exactly
    int i = pix / WW, j = pix - i*WW;
    float depth = obs[3*NPIX + pix];
    float X = ((float)j - 319.5f) * depth / fcam + 250.0f;
    float Z = ((float)(479 - i) - 239.5f) * depth / fcam + 88.0f;
    float xs = (X/5.0f - 50.0f)/100.0f*2.0f;
    float ys = (depth/5.0f - 50.0f)/100.0f*2.0f;
    float zs = (Z/5.0f - 32.0f)/80.0f*2.0f;
    float pos0 = xs*100.0f/2.0f + 50.0f;
    float pos1 = ys*100.0f/2.0f + 50.0f;
    float pos2 = zs*80.0f/2.0f + 40.0f;
    float fl0 = floorf(pos0), fl1 = floorf(pos1), fl2 = floorf(pos2);
    float ft1 = obs[4*NPIX+pix], ft2 = obs[5*NPIX+pix], ft3 = obs[6*NPIX+pix];
    float ft4 = obs[7*NPIX+pix], ft5 = obs[8*NPIX+pix];

    #pragma unroll
    for (int c0=0;c0<2;c0++){
        float p0 = fl0 + (float)c0;
        if (!(p0 > 0.0f && p0 < 100.0f)) continue;
        float w0 = 1.0f - fabsf(pos0 - p0);
        #pragma unroll
        for (int c1=0;c1<2;c1++){
            float p1 = fl1 + (float)c1;
            if (!(p1 > 0.0f && p1 < 100.0f)) continue;
            float w01 = w0 * (1.0f - fabsf(pos1 - p1));
            #pragma unroll
            for (int c2=0;c2<2;c2++){
                float p2 = fl2 + (float)c2;
                if (!(p2 > 0.0f && p2 < 80.0f)) continue;
                float w = w01 * (1.0f - fabsf(pos2 - p2));
                int idx = (((int)p0)*100 + (int)p1)*80 + (int)p2;
                float* base = g_vox2 + (size_t)idx*8;
                red_v4(base,     w, ft1*w, ft2*w, ft3*w);
                red_v2(base + 4, ft4*w, ft5*w);
            }
        }
    }

    // ---- ks block max (channels 4..7 == ft1..ft4) ----
    float m1=ft1, m2=ft2, m3=ft3, m4=ft4;
    #pragma unroll
    for (int off=16; off; off>>=1) {
        m1 = fmaxf(m1, __shfl_xor_sync(0xffffffffu, m1, off));
        m2 = fmaxf(m2, __shfl_xor_sync(0xffffffffu, m2, off));
        m3 = fmaxf(m3, __shfl_xor_sync(0xffffffffu, m3, off));
        m4 = fmaxf(m4, __shfl_xor_sync(0xffffffffu, m4, off));
    }
    int lane = tid & 31, wid = tid >> 5;
    if (lane == 0) { smax[wid][0]=m1; smax[wid][1]=m2; smax[wid][2]=m3; smax[wid][3]=m4; }
    __syncthreads();
    if (tid < 4) {
        float v = smax[0][tid];
        #pragma unroll
        for (int w=1; w<8; w++) v = fmaxf(v, smax[w][tid]);
        g_bmax[tid*SPLAT_BLOCKS + blockIdx.x] = v;
    }
}

// ---------------------------------------------------------------- round + z-sums (+rezero, +ks final)
__global__ __launch_bounds__(256) void reduce_kernel(float* __restrict__ out_fp) {
    int gid = blockIdx.x*256 + threadIdx.x;
    if (gid < 40000) {
        int colq = gid >> 2, q = gid & 3;               // 4 threads per column
        int a = colq / 100, b = colq - a*100;           // t = a*100+b ; voxel col = b*100+a
        size_t vbase = ((size_t)(b*100 + a)*80 + q*20)*8;
        float allv[6] = {0,0,0,0,0,0};
        float ahv [6] = {0,0,0,0,0,0};
        const float4 z4 = make_float4(0.f,0.f,0.f,0.f);
        #pragma unroll 4
        for (int z=0; z<20; z++) {
            float4 v0 = *reinterpret_cast<float4*>(g_vox2 + vbase + z*8);
            float4 v1 = *reinterpret_cast<float4*>(g_vox2 + vbase + z*8 + 4);
            *reinterpret_cast<float4*>(g_vox2 + vbase + z*8)     = z4;   // rezero for next replay
            *reinterpret_cast<float4*>(g_vox2 + vbase + z*8 + 4) = z4;
            float r[6];
            r[0]=rintf(v0.x); r[1]=rintf(v0.y); r[2]=rintf(v0.z);
            r[3]=rintf(v0.w); r[4]=rintf(v1.x); r[5]=rintf(v1.y);
            int zg = q*20 + z;
            bool in = (zg >= 13) && (zg < 25);
            #pragma unroll
            for (int c=0;c<6;c++){ allv[c]+=r[c]; if (in) ahv[c]+=r[c]; }
        }
        #pragma unroll
        for (int c=0;c<6;c++){
            allv[c] += __shfl_down_sync(0xffffffffu, allv[c], 2);
            allv[c] += __shfl_down_sync(0xffffffffu, allv[c], 1);
            ahv [c] += __shfl_down_sync(0xffffffffu, ahv [c], 2);
            ahv [c] += __shfl_down_sync(0xffffffffu, ahv [c], 1);
        }
        if (q == 0) {
            float r0 = fminf(fmaxf(ahv[0],  0.f), 1.f);   // fp_map
            g_av[          colq] = r0;
            g_av[  10000 + colq] = fminf(fmaxf(allv[0], 0.f), 1.f);   // fp_exp
            #pragma unroll
            for (int c=1;c<6;c++)
                g_av[(1+c)*10000 + colq] = fminf(fmaxf(ahv[c]/5.0f, 0.f), 1.f);
            out_fp[colq] = r0;
        }
    } else {
        int kid = gid - 40000;                 // last block, threads 64..191: warp-aligned
        if (kid < 128) {
            int ch = kid >> 5, lane = kid & 31;
            float m = 0.0f;
            for (int i = lane; i < SPLAT_BLOCKS; i += 32)
                m = fmaxf(m, g_bmax[ch*SPLAT_BLOCKS + i]);
            #pragma unroll
            for (int off=16; off; off>>=1) m = fmaxf(m, __shfl_xor_sync(0xffffffffu, m, off));
            if (lane == 0) g_ks[ch] = m;
        }
    }
}

// ---------------------------------------------------------------- rotation resample (support window only)
__global__ __launch_bounds__(256) void rotate_kernel() {
    int idx = blockIdx.x*256 + threadIdx.x;
    if (idx >= ROT_W*ROT_W) return;
    int i = ROT_LO + idx / ROT_W, j = ROT_LO + idx % ROT_W;
    int xmin = (int)g_params[5], xmax = (int)g_params[6];
    int ymin = (int)g_params[7], ymax = (int)g_params[8];
    if (j < xmin || j > xmax || i < ymin || i > ymax) return;   // outside: stays at prior (identical) value/zero
    float ct = g_params[1], sn = g_params[2];
    const float step = 2.0f/959.0f;
    float gx = -1.0f + (float)j*step;
    float gy = -1.0f + (float)i*step;
    float x = (ct*gx - sn*gy + 1.0f)*0.5f*959.0f;
    float y = (sn*gx + ct*gy + 1.0f)*0.5f*959.0f;
    float x0 = floorf(x), y0 = floorf(y);
    float acc[7] = {0.f,0.f,0.f,0.f,0.f,0.f,0.f};
    #pragma unroll
    for (int dy=0; dy<2; dy++){
        float yy = y0 + (float)dy;
        int yi = (int)yy;
        #pragma unroll
        for (int dx=0; dx<2; dx++){
            float xx = x0 + (float)dx;
            int xi = (int)xx;
            if (yi >= 480 && yi < 580 && xi >= 430 && xi < 530) {
                float wv = (1.0f - fabsf(x - xx)) * (1.0f - fabsf(y - yy));
                int o = (yi - 480)*100 + (xi - 430);
                #pragma unroll
                for (int c=0;c<7;c++) acc[c] += g_av[c*10000 + o] * wv;
            }
        }
    }
    #pragma unroll
    for (int c=0;c<7;c++) g_rot[c*MPIX + i*MM + j] = acc[c];
}

// ---------------------------------------------------------------- translate + sem replace + max(maps_last)
__global__ __launch_bounds__(256) void translate_kernel(const float* __restrict__ maps_last,
                                                        float* __restrict__ out_map) {
    int pix = blockIdx.x*256 + threadIdx.x;
    if (pix >= MPIX) return;
    int i = pix / MM, j = pix - i*MM;
    const float step = 2.0f/959.0f;
    float sx = g_params[3], sy = g_params[4];
    float gx = -1.0f + (float)j*step;
    float gy = -1.0f + (float)i*step;
    float x = ((gx + sx) + 1.0f)*0.5f*959.0f;
    float y = ((gy + sy) + 1.0f)*0.5f*959.0f;
    float x0 = floorf(x), y0 = floorf(y);
    float t[7] = {0.f,0.f,0.f,0.f,0.f,0.f,0.f};
    float xminf = g_params[5], xmaxf = g_params[6];
    float yminf = g_params[7], ymaxf = g_params[8];
    if (!(x0 > xmaxf || x0 + 1.0f < xminf || y0 > ymaxf || y0 + 1.0f < yminf)) {
        #pragma unroll
        for (int dy=0; dy<2; dy++){
            float yy = y0 + (float)dy;
            int yi = (int)yy;
            #pragma unroll
            for (int dx=0; dx<2; dx++){
                float xx = x0 + (float)dx;
                int xi = (int)xx;
                if (xx >= 0.0f && xx <= 959.0f && yy >= 0.0f && yy <= 959.0f) {
                    float wv = (1.0f - fabsf(x - xx)) * (1.0f - fabsf(y - yy));
                    int o = yi*MM + xi;
                    #pragma unroll
                    for (int c=0;c<7;c++) t[c] += g_rot[c*MPIX + o] * wv;
                }
            }
        }
    }
    out_map[          pix] = fmaxf(maps_last[          pix], t[0]);
    out_map[  MPIX + pix] = fmaxf(maps_last[  MPIX + pix], t[1]);
    out_map[2*MPIX + pix] = fmaxf(maps_last[2*MPIX + pix], 0.0f);  // translated ch2 == 0
    out_map[3*MPIX + pix] = fmaxf(maps_last[3*MPIX + pix], 0.0f);  // translated ch3 == 0
    #pragma unroll
    for (int k=0;k<4;k++){
        float tt = t[2+k];
        if (tt > 0.0f) tt = g_ks[k];                                // sem replacement
        out_map[(4+k)*MPIX + pix] = fmaxf(maps_last[(4+k)*MPIX + pix], tt);
    }
    out_map[8*MPIX + pix] = fmaxf(maps_last[8*MPIX + pix], t[6]);
}

// ---------------------------------------------------------------- launch
extern "C" void kernel_launch(void* const* d_in, const int* in_sizes, int n_in,
                              void* d_out, int out_size) {
    const float* obs        = (const float*)d_in[0];   // (1,9,480,640)
    const float* pose_obs   = (const float*)d_in[1];   // (3,)
    const float* maps_last  = (const float*)d_in[2];   // (9,960,960)
    const float* poses_last = (const float*)d_in[3];   // (3,)
    float* out = (float*)d_out;

    splat_kernel<<<SPLAT_BLOCKS, 256>>>(obs, pose_obs, poses_last, out);
    reduce_kernel<<<157, 256>>>(out + FP_OFF);                    // 40192 threads: 40000 cols + ks
    rotate_kernel<<<(ROT_W*ROT_W + 255)/256, 256>>>();
    translate_kernel<<<(MPIX + 255)/256, 256>>>(maps_last, out + MAP_OFF);
    (void)in_sizes; (void)n_in; (void)out_size;
}

// round 13
// speedup vs baseline: 3.1390x; 1.5805x over previous
#include <cuda_runtime.h>
#include <math.h>

#define HH 480
#define WW 640
#define NPIX (HH*WW)          // 307200
#define MM 960
#define MPIX (MM*MM)          // 921600
#define FP_OFF 0
#define MAP_OFF 10000
#define POSE_OFF (10000 + 9*MPIX)   // 8304400
#define SPLAT_BLOCKS 1200
#define ROT_LO 360
#define ROT_W 241             // covers [360,600] inclusive
#define ZW 12                 // window z slots: 13..24

// scratch (device globals: allocation-free, zero-initialized at load)
__device__ __align__(16) float g_voxw[100*100*80];      // scalar weight grid, full z (3.2MB)
__device__ __align__(32) float g_voxf[100*100*ZW*8];    // window: [col][wz][8] = w,f1..f5,pad,pad (3.84MB)
__device__ float g_av[7*10000];                // agent_view active region, ch {0,1,4,5,6,7,8}
__device__ float g_rot[7*MPIX];                // rotated image (only support window ever written)
__device__ float g_bmax[4*SPLAT_BLOCKS];       // per-block ks maxes
__device__ float g_ks[4];                      // final ks
__device__ float g_params[12];                 // 1:ct 2:sn 3:sx 4:sy 5..8: bbox

__device__ __forceinline__ void red_v4(float* p, float a, float b, float c, float d) {
    asm volatile("red.global.add.v4.f32 [%0], {%1,%2,%3,%4};"
                 :: "l"(p), "f"(a), "f"(b), "f"(c), "f"(d) : "memory");
}
__device__ __forceinline__ void red_v2(float* p, float a, float b) {
    asm volatile("red.global.add.v2.f32 [%0], {%1,%2};"
                 :: "l"(p), "f"(a), "f"(b) : "memory");
}
__device__ __forceinline__ void red_f(float* p, float a) {
    asm volatile("red.global.add.f32 [%0], %1;" :: "l"(p), "f"(a) : "memory");
}

// ---------------------------------------------------------------- splat (+pose, +ks block max)
__global__ __launch_bounds__(256) void splat_kernel(const float* __restrict__ obs,
                                                    const float* __restrict__ pose_obs,
                                                    const float* __restrict__ poses_last,
                                                    float* __restrict__ out) {
    __shared__ float sh_f;
    __shared__ float smax[8][4];
    int tid = threadIdx.x;
    if (tid == 0) {
        sh_f = (float)(320.0 / tan(39.5 * 3.141592653589793 / 180.0));
        if (blockIdx.x == 0) {
            // ---- pose + transform params (matches reference numerics) ----
            const float DEGf = 57.29577951308232f;
            float th = poses_last[2] / DEGf;
            float s = sinf(th), c = cosf(th);
            float ny = poses_last[1] + pose_obs[0]*s + pose_obs[1]*c;
            float nx = poses_last[0] + pose_obs[0]*c - pose_obs[1]*s;
            float nt = poses_last[2] + pose_obs[2]*DEGf;
            nt = fmodf(nt - 180.0f, 360.0f) + 180.0f;
            nt = fmodf(nt + 180.0f, 360.0f) - 180.0f;
            out[POSE_OFF+0] = nx; out[POSE_OFF+1] = ny; out[POSE_OFF+2] = nt;
            out[POSE_OFF+3] = nx; out[POSE_OFF+4] = ny; out[POSE_OFF+5] = nt;

            float sx = -(nx*100.0f/5.0f - 480.0f)/480.0f;
            float sy = -(ny*100.0f/5.0f - 480.0f)/480.0f;
            float sth = (90.0f - nt) * 3.14159265358979323846f / 180.0f;
            float ct = cosf(sth), sn = sinf(sth);
            g_params[1] = ct; g_params[2] = sn;
            g_params[3] = sx; g_params[4] = sy;

            const float half = 479.5f;
            float xmn=1e9f,xmx=-1e9f,ymn=1e9f,ymx=-1e9f;
            float cx[4] = {429.f,530.f,429.f,530.f};
            float cy[4] = {479.f,479.f,580.f,580.f};
            #pragma unroll
            for (int k=0;k<4;k++){
                float u = cx[k]/half - 1.0f, v = cy[k]/half - 1.0f;
                float gu =  ct*u + sn*v;
                float gv = -sn*u + ct*v;
                float jx = (gu+1.0f)*half, iy = (gv+1.0f)*half;
                xmn = fminf(xmn,jx); xmx = fmaxf(xmx,jx);
                ymn = fminf(ymn,iy); ymx = fmaxf(ymx,iy);
            }
            g_params[5] = fmaxf(floorf(xmn)-3.0f, 0.0f);
            g_params[6] = fminf(ceilf (xmx)+3.0f, 959.0f);
            g_params[7] = fmaxf(floorf(ymn)-3.0f, 0.0f);
            g_params[8] = fminf(ceilf (ymx)+3.0f, 959.0f);
        }
    }
    __syncthreads();
    float fcam = sh_f;

    int pix = blockIdx.x*256 + tid;             // NPIX == SPLAT_BLOCKS*256 exactly
    int i = pix / WW, j = pix - i*WW;
    float depth = obs[3*NPIX + pix];
    float X = ((float)j - 319.5f) * depth / fcam + 250.0f;
    float Z = ((float)(479 - i) - 239.5f) * depth / fcam + 88.0f;
    float xs = (X/5.0f - 50.0f)/100.0f*2.0f;
    float ys = (depth/5.0f - 50.0f)/100.0f*2.0f;
    float zs = (Z/5.0f - 32.0f)/80.0f*2.0f;
    float pos0 = xs*100.0f/2.0f + 50.0f;
    float pos1 = ys*100.0f/2.0f + 50.0f;
    float pos2 = zs*80.0f/2.0f + 40.0f;
    float fl0 = floorf(pos0), fl1 = floorf(pos1), fl2 = floorf(pos2);
    float ft1 = obs[4*NPIX+pix], ft2 = obs[5*NPIX+pix], ft3 = obs[6*NPIX+pix];
    float ft4 = obs[7*NPIX+pix], ft5 = obs[8*NPIX+pix];

    #pragma unroll
    for (int c0=0;c0<2;c0++){
        float p0 = fl0 + (float)c0;
        if (!(p0 > 0.0f && p0 < 100.0f)) continue;
        float w0 = 1.0f - fabsf(pos0 - p0);
        #pragma unroll
        for (int c1=0;c1<2;c1++){
            float p1 = fl1 + (float)c1;
            if (!(p1 > 0.0f && p1 < 100.0f)) continue;
            float w01 = w0 * (1.0f - fabsf(pos1 - p1));
            int col = ((int)p0)*100 + (int)p1;
            #pragma unroll
            for (int c2=0;c2<2;c2++){
                float p2 = fl2 + (float)c2;
                if (!(p2 > 0.0f && p2 < 80.0f)) continue;
                float w = w01 * (1.0f - fabsf(pos2 - p2));
                int z = (int)p2;
                if (z >= 13 && z < 25) {
                    // window voxel: weight + all 5 features, interleaved
                    float* base = g_voxf + ((size_t)col*ZW + (z-13))*8;
                    red_v4(base,     w, ft1*w, ft2*w, ft3*w);
                    red_v2(base + 4, ft4*w, ft5*w);
                } else {
                    // outside window: only the weight channel ever matters
                    red_f(g_voxw + (size_t)col*80 + z, w);
                }
            }
        }
    }

    // ---- ks block max (channels 4..7 == ft1..ft4) ----
    float m1=ft1, m2=ft2, m3=ft3, m4=ft4;
    #pragma unroll
    for (int off=16; off; off>>=1) {
        m1 = fmaxf(m1, __shfl_xor_sync(0xffffffffu, m1, off));
        m2 = fmaxf(m2, __shfl_xor_sync(0xffffffffu, m2, off));
        m3 = fmaxf(m3, __shfl_xor_sync(0xffffffffu, m3, off));
        m4 = fmaxf(m4, __shfl_xor_sync(0xffffffffu, m4, off));
    }
    int lane = tid & 31, wid = tid >> 5;
    if (lane == 0) { smax[wid][0]=m1; smax[wid][1]=m2; smax[wid][2]=m3; smax[wid][3]=m4; }
    __syncthreads();
    if (tid < 4) {
        float v = smax[0][tid];
        #pragma unroll
        for (int w=1; w<8; w++) v = fmaxf(v, smax[w][tid]);
        g_bmax[tid*SPLAT_BLOCKS + blockIdx.x] = v;
    }
}

// ---------------------------------------------------------------- round + z-sums (+rezero, +ks final)
__global__ __launch_bounds__(256) void reduce_kernel(float* __restrict__ out_fp) {
    int gid = blockIdx.x*256 + threadIdx.x;
    if (gid < 10000) {
        int tv = gid;                       // voxel column index = b*100 + a
        int b = tv / 100, a = tv - b*100;
        int t = a*100 + b;                  // output/agent-view index
        const float4 z4 = make_float4(0.f,0.f,0.f,0.f);

        // full-z scalar weights (window slots are zero; rintf(0)=0)
        float allw = 0.f;
        float4* wp = reinterpret_cast<float4*>(g_voxw + (size_t)tv*80);
        #pragma unroll 5
        for (int zi = 0; zi < 20; zi++) {
            float4 v = wp[zi];
            wp[zi] = z4;                    // rezero for next graph replay
            allw += rintf(v.x) + rintf(v.y) + rintf(v.z) + rintf(v.w);
        }

        // window voxels: weight + 5 features
        float ahw = 0.f, ahf[5] = {0.f,0.f,0.f,0.f,0.f};
        float4* fp = reinterpret_cast<float4*>(g_voxf + (size_t)tv*ZW*8);
        #pragma unroll
        for (int wz = 0; wz < ZW; wz++) {
            float4 v0 = fp[wz*2], v1 = fp[wz*2+1];
            fp[wz*2] = z4; fp[wz*2+1] = z4;
            float r0 = rintf(v0.x);
            ahw += r0;
            ahf[0] += rintf(v0.y); ahf[1] += rintf(v0.z); ahf[2] += rintf(v0.w);
            ahf[3] += rintf(v1.x); ahf[4] += rintf(v1.y);
        }
        allw += ahw;

        float r0 = fminf(fmaxf(ahw,  0.f), 1.f);       // fp_map
        g_av[          t] = r0;
        g_av[  10000 + t] = fminf(fmaxf(allw, 0.f), 1.f);  // fp_exp
        #pragma unroll
        for (int c=0;c<5;c++)
            g_av[(2+c)*10000 + t] = fminf(fmaxf(ahf[c]/5.0f, 0.f), 1.f);
        out_fp[t] = r0;
    } else {
        int kid = gid - 10000;
        if (kid < 128) {
            int ch = kid >> 5, lane = kid & 31;
            float m = 0.0f;
            for (int i = lane; i < SPLAT_BLOCKS; i += 32)
                m = fmaxf(m, g_bmax[ch*SPLAT_BLOCKS + i]);
            #pragma unroll
            for (int off=16; off; off>>=1) m = fmaxf(m, __shfl_xor_sync(0xffffffffu, m, off));
            if (lane == 0) g_ks[ch] = m;
        }
    }
}

// ---------------------------------------------------------------- rotation resample (support window only)
__global__ __launch_bounds__(256) void rotate_kernel() {
    int idx = blockIdx.x*256 + threadIdx.x;
    if (idx >= ROT_W*ROT_W) return;
    int i = ROT_LO + idx / ROT_W, j = ROT_LO + idx % ROT_W;
    int xmin = (int)g_params[5], xmax = (int)g_params[6];
    int ymin = (int)g_params[7], ymax = (int)g_params[8];
    if (j < xmin || j > xmax || i < ymin || i > ymax) return;
    float ct = g_params[1], sn = g_params[2];
    const float step = 2.0f/959.0f;
    float gx = -1.0f + (float)j*step;
    float gy = -1.0f + (float)i*step;
    float x = (ct*gx - sn*gy + 1.0f)*0.5f*959.0f;
    float y = (sn*gx + ct*gy + 1.0f)*0.5f*959.0f;
    float x0 = floorf(x), y0 = floorf(y);
    float acc[7] = {0.f,0.f,0.f,0.f,0.f,0.f,0.f};
    #pragma unroll
    for (int dy=0; dy<2; dy++){
        float yy = y0 + (float)dy;
        int yi = (int)yy;
        #pragma unroll
        for (int dx=0; dx<2; dx++){
            float xx = x0 + (float)dx;
            int xi = (int)xx;
            if (yi >= 480 && yi < 580 && xi >= 430 && xi < 530) {
                float wv = (1.0f - fabsf(x - xx)) * (1.0f - fabsf(y - yy));
                int o = (yi - 480)*100 + (xi - 430);
                #pragma unroll
                for (int c=0;c<7;c++) acc[c] += g_av[c*10000 + o] * wv;
            }
        }
    }
    #pragma unroll
    for (int c=0;c<7;c++) g_rot[c*MPIX + i*MM + j] = acc[c];
}

// ---------------------------------------------------------------- translate + sem replace + max(maps_last)
// 4 pixels per thread, float4 traffic on maps_last / out_map.
__global__ __launch_bounds__(256) void translate_kernel(const float* __restrict__ maps_last,
                                                        float* __restrict__ out_map) {
    int idx = blockIdx.x*256 + threadIdx.x;        // 230400 threads
    if (idx >= MPIX/4) return;
    int i = idx / (MM/4);
    int j0 = (idx - i*(MM/4)) * 4;
    int pix0 = i*MM + j0;

    const float step = 2.0f/959.0f;
    float sx = g_params[3], sy = g_params[4];
    float xminf = g_params[5], xmaxf = g_params[6];
    float yminf = g_params[7], ymaxf = g_params[8];
    float gy = -1.0f + (float)i*step;
    float y = ((gy + sy) + 1.0f)*0.5f*959.0f;
    float y0 = floorf(y);

    float t[4][7];
    #pragma unroll
    for (int l=0;l<4;l++)
        #pragma unroll
        for (int c=0;c<7;c++) t[l][c] = 0.f;

    if (!(y0 > ymaxf || y0 + 1.0f < yminf)) {
        #pragma unroll
        for (int l=0;l<4;l++){
            float gx = -1.0f + (float)(j0+l)*step;
            float x = ((gx + sx) + 1.0f)*0.5f*959.0f;
            float x0 = floorf(x);
            if (x0 > xmaxf || x0 + 1.0f < xminf) continue;
            #pragma unroll
            for (int dy=0; dy<2; dy++){
                float yy = y0 + (float)dy;
                int yi = (int)yy;
                #pragma unroll
                for (int dx=0; dx<2; dx++){
                    float xx = x0 + (float)dx;
                    int xi = (int)xx;
                    if (xx >= 0.0f && xx <= 959.0f && yy >= 0.0f && yy <= 959.0f) {
                        float wv = (1.0f - fabsf(x - xx)) * (1.0f - fabsf(y - yy));
                        int o = yi*MM + xi;
                        #pragma unroll
                        for (int c=0;c<7;c++) t[l][c] += g_rot[c*MPIX + o] * wv;
                    }
                }
            }
        }
    }

    // channel mapping: t[.][0]->out ch0, t[.][1]->ch1, t[.][2..5]->ch4..7 (sem), t[.][6]->ch8
    const float4* ml = reinterpret_cast<const float4*>(maps_last);
    float4*       om = reinterpret_cast<float4*>(out_map);
    int v = pix0 >> 2;
    const int VCH = MPIX/4;
    {   float4 m = ml[v];
        om[v] = make_float4(fmaxf(m.x,t[0][0]), fmaxf(m.y,t[1][0]), fmaxf(m.z,t[2][0]), fmaxf(m.w,t[3][0])); }
    {   float4 m = ml[VCH + v];
        om[VCH + v] = make_float4(fmaxf(m.x,t[0][1]), fmaxf(m.y,t[1][1]), fmaxf(m.z,t[2][1]), fmaxf(m.w,t[3][1])); }
    {   float4 m = ml[2*VCH + v];
        om[2*VCH + v] = make_float4(fmaxf(m.x,0.f), fmaxf(m.y,0.f), fmaxf(m.z,0.f), fmaxf(m.w,0.f)); }
    {   float4 m = ml[3*VCH + v];
        om[3*VCH + v] = make_float4(fmaxf(m.x,0.f), fmaxf(m.y,0.f), fmaxf(m.z,0.f), fmaxf(m.w,0.f)); }
    #pragma unroll
    for (int k=0;k<4;k++){
        float ks = g_ks[k];
        float4 m = ml[(4+k)*VCH + v];
        float s0 = t[0][2+k] > 0.0f ? ks : t[0][2+k];
        float s1 = t[1][2+k] > 0.0f ? ks : t[1][2+k];
        float s2 = t[2][2+k] > 0.0f ? ks : t[2][2+k];
        float s3 = t[3][2+k] > 0.0f ? ks : t[3][2+k];
        om[(4+k)*VCH + v] = make_float4(fmaxf(m.x,s0), fmaxf(m.y,s1), fmaxf(m.z,s2), fmaxf(m.w,s3));
    }
    {   float4 m = ml[8*VCH + v];
        om[8*VCH + v] = make_float4(fmaxf(m.x,t[0][6]), fmaxf(m.y,t[1][6]), fmaxf(m.z,t[2][6]), fmaxf(m.w,t[3][6])); }
}

// ---------------------------------------------------------------- launch
extern "C" void kernel_launch(void* const* d_in, const int* in_sizes, int n_in,
                              void* d_out, int out_size) {
    const float* obs        = (const float*)d_in[0];   // (1,9,480,640)
    const float* pose_obs   = (const float*)d_in[1];   // (3,)
    const float* maps_last  = (const float*)d_in[2];   // (9,960,960)
    const float* poses_last = (const float*)d_in[3];   // (3,)
    float* out = (float*)d_out;

    splat_kernel<<<SPLAT_BLOCKS, 256>>>(obs, pose_obs, poses_last, out);
    reduce_kernel<<<40, 256>>>(out + FP_OFF);                 // 10240 threads: 10000 cols + ks
    rotate_kernel<<<(ROT_W*ROT_W + 255)/256, 256>>>();
    translate_kernel<<<(MPIX/4 + 255)/256, 256>>>(maps_last, out + MAP_OFF);
    (void)in_sizes; (void)n_in; (void)out_size;
}